// round 2
// baseline (speedup 1.0000x reference)
#include <cuda_runtime.h>

#define N_SUBDOCS 4096
#define N_WORDS   128
#define DIM       768
#define N_DOCS    256
#define GRID1     444   // 148 SMs * 3 resident CTAs -> persistent, no wave tail

// scratch for per-subdoc pooled logits (allocation-free per harness rules)
__device__ float g_zpool[N_SUBDOCS];

// Kernel 1: per-subdoc word softmax-pool, persistent grid-stride.
// 512 threads (16 warps); each warp handles 8 words of the current subdoc.
// W held in registers. Double-buffered word-logit array -> 1 sync per subdoc.
__global__ __launch_bounds__(512) void pool_words_kernel(
    const float* __restrict__ emb,   // [N_SUBDOCS, N_WORDS, DIM]
    const float* __restrict__ W,     // [DIM]
    const float* __restrict__ b,     // [1]
    const float* __restrict__ logt,  // [1]
    float* __restrict__ zpool)       // [N_SUBDOCS]
{
    __shared__ float sz[2][N_WORDS];

    const int tid  = threadIdx.x;
    const int lane = tid & 31;
    const int warp = tid >> 5;

    // W in registers: lane i holds W4[i], W4[i+32], ..., W4[i+160]
    float4 wreg[6];
    const float4* W4 = reinterpret_cast<const float4*>(W);
    #pragma unroll
    for (int i = 0; i < 6; i++) wreg[i] = W4[lane + i * 32];
    const float bias = b[0];
    const float t    = expf(logt[0]);

    int p = 0;
    for (int n = blockIdx.x; n < N_SUBDOCS; n += GRID1, p ^= 1) {
        const float* base = emb + (size_t)n * (N_WORDS * DIM);

        #pragma unroll
        for (int w = warp; w < N_WORDS; w += 16) {
            const float4* row = reinterpret_cast<const float4*>(base + w * DIM);
            float acc = 0.f;
            #pragma unroll
            for (int i = 0; i < 6; i++) {
                float4 e = __ldcs(&row[lane + i * 32]);   // streaming, evict-first
                acc += e.x * wreg[i].x + e.y * wreg[i].y
                     + e.z * wreg[i].z + e.w * wreg[i].w;
            }
            #pragma unroll
            for (int o = 16; o; o >>= 1)
                acc += __shfl_xor_sync(0xffffffffu, acc, o);
            if (lane == 0) sz[p][w] = acc + bias;
        }
        __syncthreads();

        // Warp 0: softmax-pool over 128 word logits of buffer p, while the
        // other warps proceed to stream the next subdoc into buffer p^1.
        // (Safe: writes to sz[p] for subdoc n+2 happen only after the sync of
        // subdoc n+1, which warp 0 reaches only after finishing this read.)
        if (warp == 0) {
            float v[4];
            float m = -1e30f;
            #pragma unroll
            for (int i = 0; i < 4; i++) {
                v[i] = sz[p][lane + 32 * i];
                m = fmaxf(m, t * v[i]);
            }
            #pragma unroll
            for (int o = 16; o; o >>= 1)
                m = fmaxf(m, __shfl_xor_sync(0xffffffffu, m, o));
            float se = 0.f, sn = 0.f;
            #pragma unroll
            for (int i = 0; i < 4; i++) {
                float e = expf(t * v[i] - m);
                se += e;
                sn += v[i] * e;
            }
            #pragma unroll
            for (int o = 16; o; o >>= 1) {
                se += __shfl_xor_sync(0xffffffffu, se, o);
                sn += __shfl_xor_sync(0xffffffffu, sn, o);
            }
            if (lane == 0) zpool[n] = sn / se;
        }
    }
}

// Kernel 2: ragged segment softmax-pool over subdocs + sigmoid.
// 16 CTAs x 256 threads; each 16-lane group owns one document.
__global__ __launch_bounds__(256) void pool_docs_kernel(
    const float* __restrict__ zpool,  // [N_SUBDOCS]
    const int* __restrict__ lens,     // [N_DOCS]
    const float* __restrict__ logt,   // [1]
    float* __restrict__ out)          // [N_DOCS]
{
    __shared__ int scan[N_DOCS];
    const int tid = threadIdx.x;
    scan[tid] = lens[tid];
    __syncthreads();

    // Hillis-Steele inclusive scan of all 256 lengths (cheap, per-CTA)
    for (int d = 1; d < N_DOCS; d <<= 1) {
        int v = (tid >= d) ? scan[tid - d] : 0;
        __syncthreads();
        scan[tid] += v;
        __syncthreads();
    }

    const int group = tid >> 4;                 // 0..15
    const int sub   = tid & 15;
    const int doc   = blockIdx.x * 16 + group;  // 16 CTAs -> 256 docs

    const int end   = scan[doc];
    const int start = doc ? scan[doc - 1] : 0;
    const float t   = expf(logt[0]);

    float m = -1e30f;
    for (int i = start + sub; i < end; i += 16)
        m = fmaxf(m, t * zpool[i]);
    #pragma unroll
    for (int o = 8; o; o >>= 1)
        m = fmaxf(m, __shfl_xor_sync(0xffffffffu, m, o));

    float se = 0.f, sn = 0.f;
    for (int i = start + sub; i < end; i += 16) {
        float z = zpool[i];
        float e = expf(t * z - m);
        se += e;
        sn += z * e;
    }
    #pragma unroll
    for (int o = 8; o; o >>= 1) {
        se += __shfl_xor_sync(0xffffffffu, se, o);
        sn += __shfl_xor_sync(0xffffffffu, sn, o);
    }

    if (sub == 0) {
        float zp = sn / se;
        out[doc] = 1.f / (1.f + expf(-zp));
    }
}

extern "C" void kernel_launch(void* const* d_in, const int* in_sizes, int n_in,
                              void* d_out, int out_size) {
    const float* emb  = (const float*)d_in[0];  // embeddings [4096,128,768] f32
    const float* W    = (const float*)d_in[1];  // [1,768] f32
    const float* b    = (const float*)d_in[2];  // [1] f32
    const float* logt = (const float*)d_in[3];  // [1] f32
    const int*   lens = (const int*)d_in[4];    // [256] i32
    float* out = (float*)d_out;                 // [256] f32

    float* zpool = nullptr;
    cudaGetSymbolAddress((void**)&zpool, g_zpool);

    pool_words_kernel<<<GRID1, 512>>>(emb, W, b, logt, zpool);
    pool_docs_kernel<<<16, 256>>>(zpool, lens, logt, out);
}

// round 3
// speedup vs baseline: 1.0998x; 1.0998x over previous
#include <cuda_runtime.h>

#define N_SUBDOCS 4096
#define N_WORDS   128
#define DIM       768
#define N_DOCS    256

// scratch for per-subdoc pooled logits + completion counter (allocation-free)
__device__ float g_zpool[N_SUBDOCS];
__device__ unsigned int g_done;   // zero-initialized at module load; reset each run

// One CTA per subdoc, 512 threads (16 warps). Each warp handles 8 words.
// W kept in registers. The LAST CTA to finish also performs the ragged
// segment softmax-pool over subdocs + sigmoid (epilogue fused, no 2nd launch).
__global__ __launch_bounds__(512) void pool_kernel(
    const float* __restrict__ emb,   // [N_SUBDOCS, N_WORDS, DIM]
    const float* __restrict__ W,     // [DIM]
    const float* __restrict__ b,     // [1]
    const float* __restrict__ logt,  // [1]
    const int* __restrict__ lens,    // [N_DOCS]
    float* __restrict__ out)         // [N_DOCS]
{
    __shared__ float sz[N_WORDS];
    __shared__ int   scan[N_DOCS];
    __shared__ int   is_last;

    const int tid  = threadIdx.x;
    const int lane = tid & 31;
    const int warp = tid >> 5;

    // W in registers: lane i holds W4[i], W4[i+32], ..., W4[i+160]
    float4 wreg[6];
    const float4* W4 = reinterpret_cast<const float4*>(W);
    #pragma unroll
    for (int i = 0; i < 6; i++) wreg[i] = W4[lane + i * 32];
    const float bias = b[0];
    const float t    = expf(logt[0]);

    const float* base = emb + (size_t)blockIdx.x * (N_WORDS * DIM);

    #pragma unroll
    for (int w = warp; w < N_WORDS; w += 16) {
        const float4* row = reinterpret_cast<const float4*>(base + w * DIM);
        float acc = 0.f;
        #pragma unroll
        for (int i = 0; i < 6; i++) {
            float4 e = row[lane + i * 32];
            acc += e.x * wreg[i].x + e.y * wreg[i].y
                 + e.z * wreg[i].z + e.w * wreg[i].w;
        }
        #pragma unroll
        for (int o = 16; o; o >>= 1)
            acc += __shfl_xor_sync(0xffffffffu, acc, o);
        if (lane == 0) sz[w] = acc + bias;
    }
    __syncthreads();

    // Warp 0: softmax-pool over the 128 word logits: sum(z * softmax(t*z))
    if (warp == 0) {
        float v[4];
        float m = -1e30f;
        #pragma unroll
        for (int i = 0; i < 4; i++) {
            v[i] = sz[lane + 32 * i];
            m = fmaxf(m, t * v[i]);
        }
        #pragma unroll
        for (int o = 16; o; o >>= 1)
            m = fmaxf(m, __shfl_xor_sync(0xffffffffu, m, o));
        float se = 0.f, sn = 0.f;
        #pragma unroll
        for (int i = 0; i < 4; i++) {
            float e = expf(t * v[i] - m);
            se += e;
            sn += v[i] * e;
        }
        #pragma unroll
        for (int o = 16; o; o >>= 1) {
            se += __shfl_xor_sync(0xffffffffu, se, o);
            sn += __shfl_xor_sync(0xffffffffu, sn, o);
        }
        if (lane == 0) g_zpool[blockIdx.x] = sn / se;
    }

    // ── Completion handshake: last CTA to arrive runs the doc-pool epilogue ──
    // tid 0 is the same thread that wrote g_zpool[blockIdx.x] above, so
    // program order + __threadfence makes that write visible before the
    // atomic increment (release). No extra barrier needed before the atomic.
    if (tid == 0) {
        __threadfence();
        unsigned int old = atomicAdd(&g_done, 1u);
        is_last = (old == (unsigned int)(gridDim.x - 1));
    }
    __syncthreads();
    if (!is_last) return;

    if (tid == 0) g_done = 0;   // reset for the next graph replay
    __threadfence();            // acquire: all CTAs' g_zpool writes visible

    // Inclusive scan of subdoc lengths (ragged segment offsets)
    if (tid < N_DOCS) scan[tid] = lens[tid];
    __syncthreads();
    for (int d = 1; d < N_DOCS; d <<= 1) {
        int v = (tid >= d && tid < N_DOCS) ? scan[tid - d] : 0;
        __syncthreads();
        if (tid < N_DOCS) scan[tid] += v;
        __syncthreads();
    }

    // 32 groups of 16 lanes; each group handles docs group, group+32, ...
    const int group = tid >> 4;   // 0..31
    const int sub   = tid & 15;

    for (int doc = group; doc < N_DOCS; doc += 32) {
        const int end   = scan[doc];
        const int start = doc ? scan[doc - 1] : 0;

        float m = -1e30f;
        for (int i = start + sub; i < end; i += 16)
            m = fmaxf(m, t * g_zpool[i]);
        #pragma unroll
        for (int o = 8; o; o >>= 1)
            m = fmaxf(m, __shfl_xor_sync(0xffffffffu, m, o));

        float se = 0.f, sn = 0.f;
        for (int i = start + sub; i < end; i += 16) {
            float z = g_zpool[i];
            float e = expf(t * z - m);
            se += e;
            sn += z * e;
        }
        #pragma unroll
        for (int o = 8; o; o >>= 1) {
            se += __shfl_xor_sync(0xffffffffu, se, o);
            sn += __shfl_xor_sync(0xffffffffu, sn, o);
        }

        if (sub == 0) {
            float zp = sn / se;
            out[doc] = 1.f / (1.f + expf(-zp));
        }
    }
}

extern "C" void kernel_launch(void* const* d_in, const int* in_sizes, int n_in,
                              void* d_out, int out_size) {
    const float* emb  = (const float*)d_in[0];  // embeddings [4096,128,768] f32
    const float* W    = (const float*)d_in[1];  // [1,768] f32
    const float* b    = (const float*)d_in[2];  // [1] f32
    const float* logt = (const float*)d_in[3];  // [1] f32
    const int*   lens = (const int*)d_in[4];    // [256] i32
    float* out = (float*)d_out;                 // [256] f32

    pool_kernel<<<N_SUBDOCS, 512>>>(emb, W, b, logt, lens, out);
}

// round 4
// speedup vs baseline: 1.1732x; 1.0667x over previous
#include <cuda_runtime.h>

#define N_SUBDOCS 4096
#define N_WORDS   128
#define DIM       768
#define N_DOCS    256

// scratch for per-subdoc pooled logits (allocation-free per harness rules)
__device__ float g_zpool[N_SUBDOCS];

// Kernel 1: per-subdoc word softmax-pool.
// One CTA per subdoc, 512 threads (16 warps), each warp handles 8 words.
// W lives in SHARED memory (frees ~24 regs -> 4 CTAs/SM, occ ~100%).
__global__ __launch_bounds__(512, 4) void pool_words_kernel(
    const float* __restrict__ emb,   // [N_SUBDOCS, N_WORDS, DIM]
    const float* __restrict__ W,     // [DIM]
    const float* __restrict__ b,     // [1]
    const float* __restrict__ logt,  // [1]
    float* __restrict__ zpool)       // [N_SUBDOCS]
{
    __shared__ float sW[DIM];
    __shared__ float sz[N_WORDS];

    const int tid  = threadIdx.x;
    const int lane = tid & 31;
    const int warp = tid >> 5;

    // Stage W into shared memory once per CTA
    if (tid < DIM) sW[tid] = W[tid];
    if (tid + 512 < DIM) sW[tid + 512] = W[tid + 512];
    __syncthreads();

    const float4* sW4 = reinterpret_cast<const float4*>(sW);
    const float* base = emb + (size_t)blockIdx.x * (N_WORDS * DIM);

    #pragma unroll
    for (int w = warp; w < N_WORDS; w += 16) {
        const float4* row = reinterpret_cast<const float4*>(base + w * DIM);
        float acc = 0.f;
        #pragma unroll
        for (int i = 0; i < 6; i++) {
            float4 e  = row[lane + i * 32];
            float4 ws = sW4[lane + i * 32];
            acc += e.x * ws.x + e.y * ws.y + e.z * ws.z + e.w * ws.w;
        }
        #pragma unroll
        for (int o = 16; o; o >>= 1)
            acc += __shfl_xor_sync(0xffffffffu, acc, o);
        if (lane == 0) sz[w] = acc;     // bias added in the pooling warp
    }
    __syncthreads();

    // Warp 0: softmax-pool over the 128 word logits: sum(z * softmax(t*z))
    if (warp == 0) {
        const float bias = b[0];
        const float t    = expf(logt[0]);
        float v[4];
        float m = -1e30f;
        #pragma unroll
        for (int i = 0; i < 4; i++) {
            v[i] = sz[lane + 32 * i] + bias;
            m = fmaxf(m, t * v[i]);
        }
        #pragma unroll
        for (int o = 16; o; o >>= 1)
            m = fmaxf(m, __shfl_xor_sync(0xffffffffu, m, o));
        float se = 0.f, sn = 0.f;
        #pragma unroll
        for (int i = 0; i < 4; i++) {
            float e = expf(t * v[i] - m);
            se += e;
            sn += v[i] * e;
        }
        #pragma unroll
        for (int o = 16; o; o >>= 1) {
            se += __shfl_xor_sync(0xffffffffu, se, o);
            sn += __shfl_xor_sync(0xffffffffu, sn, o);
        }
        if (lane == 0) zpool[blockIdx.x] = sn / se;
    }
}

// Kernel 2: ragged segment softmax-pool over subdocs + sigmoid.
// 16 CTAs x 256 threads; each 16-lane group owns one document. (5.4us measured)
__global__ __launch_bounds__(256) void pool_docs_kernel(
    const float* __restrict__ zpool,  // [N_SUBDOCS]
    const int* __restrict__ lens,     // [N_DOCS]
    const float* __restrict__ logt,   // [1]
    float* __restrict__ out)          // [N_DOCS]
{
    __shared__ int scan[N_DOCS];
    const int tid = threadIdx.x;
    scan[tid] = lens[tid];
    __syncthreads();

    // Hillis-Steele inclusive scan of all 256 lengths
    for (int d = 1; d < N_DOCS; d <<= 1) {
        int v = (tid >= d) ? scan[tid - d] : 0;
        __syncthreads();
        scan[tid] += v;
        __syncthreads();
    }

    const int group = tid >> 4;                 // 0..15
    const int sub   = tid & 15;
    const int doc   = blockIdx.x * 16 + group;  // 16 CTAs -> 256 docs

    const int end   = scan[doc];
    const int start = doc ? scan[doc - 1] : 0;
    const float t   = expf(logt[0]);

    float m = -1e30f;
    for (int i = start + sub; i < end; i += 16)
        m = fmaxf(m, t * zpool[i]);
    #pragma unroll
    for (int o = 8; o; o >>= 1)
        m = fmaxf(m, __shfl_xor_sync(0xffffffffu, m, o));

    float se = 0.f, sn = 0.f;
    for (int i = start + sub; i < end; i += 16) {
        float z = zpool[i];
        float e = expf(t * z - m);
        se += e;
        sn += z * e;
    }
    #pragma unroll
    for (int o = 8; o; o >>= 1) {
        se += __shfl_xor_sync(0xffffffffu, se, o);
        sn += __shfl_xor_sync(0xffffffffu, sn, o);
    }

    if (sub == 0) {
        float zp = sn / se;
        out[doc] = 1.f / (1.f + expf(-zp));
    }
}

extern "C" void kernel_launch(void* const* d_in, const int* in_sizes, int n_in,
                              void* d_out, int out_size) {
    const float* emb  = (const float*)d_in[0];  // embeddings [4096,128,768] f32
    const float* W    = (const float*)d_in[1];  // [1,768] f32
    const float* b    = (const float*)d_in[2];  // [1] f32
    const float* logt = (const float*)d_in[3];  // [1] f32
    const int*   lens = (const int*)d_in[4];    // [256] i32
    float* out = (float*)d_out;                 // [256] f32

    float* zpool = nullptr;
    cudaGetSymbolAddress((void**)&zpool, g_zpool);

    pool_words_kernel<<<N_SUBDOCS, 512>>>(emb, W, b, logt, zpool);
    pool_docs_kernel<<<16, 256>>>(zpool, lens, logt, out);
}